// round 5
// baseline (speedup 1.0000x reference)
#include <cuda_runtime.h>

// Fused 2-layer LSTM (B=4096,S=512,F=1,H=64) + dense 64->32->24 head.
// 128 blocks x 256 threads; block owns 32 batches for the whole sequence.
// k-pair f32x2 accumulators (fold at end) -> no splat MOVs; weights LDS.64
// pairs, h as broadcast ulonglong2. GEMM2(t) -> PW2 -> GEMM1(t+1) -> BAR ->
// PW1 -> BAR with ping-pong h2; PW2 MUFU overlaps other warps' FMA via skew.

#define NT   256
#define TB   32
#define NBLK 128
#define SEQ  512

typedef unsigned long long u64;

// shared memory float offsets
#define W1_O  0                        // W_hh1 [row 0..255][pitch 66]
#define W2_O  (W1_O + 256 * 66)        // [row][pitch 130]: k<64 W_ih2, k>=64 W_hh2
#define H1_O  (W2_O + 256 * 130)       // h1 [32 b][64 k]
#define H2A_O (H1_O + 2048)            // h2 ping
#define H2B_O (H2A_O + 2048)           // h2 pong
#define XT_O  (H2B_O + 2048)           // x tile [16 t][36 pitch]
#define B1_O  (XT_O + 16 * 36)         // 256
#define B2_O  (B1_O + 256)             // 256
#define WI1_O (B2_O + 256)             // 256
#define SM_FLOATS (WI1_O + 256)
#define SM_BYTES  (SM_FLOATS * 4)      // 230656 bytes <= 232448

__device__ __forceinline__ u64 pack2(float a, float b) {
    u64 r; unsigned ua = __float_as_uint(a), ub = __float_as_uint(b);
    asm("mov.b64 %0, {%1, %2};" : "=l"(r) : "r"(ua), "r"(ub));
    return r;
}
__device__ __forceinline__ void fma2(u64& d, u64 a, u64 b) {
    asm("fma.rn.f32x2 %0, %1, %2, %0;" : "+l"(d) : "l"(a), "l"(b));
}
__device__ __forceinline__ float lo32(u64 v) { return __uint_as_float((unsigned)v); }
__device__ __forceinline__ float hi32(u64 v) { return __uint_as_float((unsigned)(v >> 32)); }

__device__ __forceinline__ float sigf(float x) {
    return __fdividef(1.f, 1.f + __expf(-x));
}
__device__ __forceinline__ float tanhf_(float x) {
    float xx = fmaxf(x, -30.f);
    float e  = __expf(-2.f * xx);
    return __fdividef(1.f - e, 1.f + e);
}

extern __shared__ float sm[];

__global__ void __launch_bounds__(NT, 1)
lstm_fused_kernel(const float* __restrict__ x,
                  const float* __restrict__ W_ih1, const float* __restrict__ W_hh1,
                  const float* __restrict__ b_ih1, const float* __restrict__ b_hh1,
                  const float* __restrict__ W_ih2, const float* __restrict__ W_hh2,
                  const float* __restrict__ b_ih2, const float* __restrict__ b_hh2,
                  const float* __restrict__ W_d1, const float* __restrict__ b_d1,
                  const float* __restrict__ W_d2, const float* __restrict__ b_d2,
                  float* __restrict__ out)
{
    const int tid  = threadIdx.x;
    const int lane = tid & 31;
    const int wrp  = tid >> 5;
    const int hid  = ((wrp & 1) << 5) | lane;   // 0..63
    const int bg   = wrp >> 1;                  // 0..3: batch octet
    const int b0   = blockIdx.x * TB;

    // ---- stage weights (row-major, padded pitch: 66 / 130) ----
    for (int i = tid; i < 16384; i += NT) {
        int r = i >> 6, k = i & 63;
        sm[W1_O + r * 66 + k] = W_hh1[i];
    }
    for (int i = tid; i < 16384; i += NT) {
        int r = i >> 6, k = i & 63;
        sm[W2_O + r * 130 + k] = W_ih2[i];
    }
    for (int i = tid; i < 16384; i += NT) {
        int r = i >> 6, k = i & 63;
        sm[W2_O + r * 130 + 64 + k] = W_hh2[i];
    }
    for (int i = tid; i < 256; i += NT) {
        sm[B1_O + i]  = b_ih1[i] + b_hh1[i];
        sm[B2_O + i]  = b_ih2[i] + b_hh2[i];
        sm[WI1_O + i] = W_ih1[i];
    }
    for (int i = tid; i < 2048; i += NT) sm[H2A_O + i] = 0.f;
    for (int i = tid; i < 512; i += NT) {
        int row = i >> 4, tq = i & 15;
        sm[XT_O + tq * 36 + row] = x[(size_t)(b0 + row) * SEQ + tq];
    }
    __syncthreads();

    float c1[8], c2[8];
    #pragma unroll
    for (int j = 0; j < 8; ++j) { c1[j] = 0.f; c2[j] = 0.f; }

    float* h1b = &sm[H1_O + bg * 512];         // this octet's h1 rows
    const int hstore = hid;                     // column within row

    // ---- prologue: h1[0] = PW(bias1 + x0 * w_ih1) ----
    {
        float4 xa = *(const float4*)&sm[XT_O + bg * 8];
        float4 xb = *(const float4*)&sm[XT_O + bg * 8 + 4];
        float xv[8] = { xa.x, xa.y, xa.z, xa.w, xb.x, xb.y, xb.z, xb.w };
        float z[4][8];
        #pragma unroll
        for (int g = 0; g < 4; ++g) {
            float wg = sm[WI1_O + g * 64 + hid], bb = sm[B1_O + g * 64 + hid];
            #pragma unroll
            for (int b = 0; b < 8; ++b) z[g][b] = fmaf(xv[b], wg, bb);
        }
        #pragma unroll
        for (int b = 0; b < 8; ++b) {
            float cc = sigf(z[1][b]) * 0.f + sigf(z[0][b]) * tanhf_(z[2][b]);
            c1[b] = cc;
            h1b[b * 64 + hstore] = sigf(z[3][b]) * tanhf_(cc);
        }
    }
    __syncthreads();

    const float* w1p0 = &sm[W1_O + (0 * 64 + hid) * 66];
    const float* w1p1 = &sm[W1_O + (1 * 64 + hid) * 66];
    const float* w1p2 = &sm[W1_O + (2 * 64 + hid) * 66];
    const float* w1p3 = &sm[W1_O + (3 * 64 + hid) * 66];
    const float* w2p0 = &sm[W2_O + (0 * 64 + hid) * 130];
    const float* w2p1 = &sm[W2_O + (1 * 64 + hid) * 130];
    const float* w2p2 = &sm[W2_O + (2 * 64 + hid) * 130];
    const float* w2p3 = &sm[W2_O + (3 * 64 + hid) * 130];

    u64 acc[4][8];

    for (int t = 0; t < SEQ; ++t) {
        if (((t + 1) & 15) == 0 && (t + 1) < SEQ) {
            int base = t + 1;
            for (int i = tid; i < 512; i += NT) {
                int row = i >> 4, tq = i & 15;
                sm[XT_O + tq * 36 + row] = x[(size_t)(b0 + row) * SEQ + base + tq];
            }
            __syncthreads();
        }

        float*       h2w = &sm[((t & 1) ? H2A_O : H2B_O) + bg * 512];
        const float* h2r = &sm[((t & 1) ? H2B_O : H2A_O) + bg * 512];

        // ============ GEMM2(t): z2 = b2 + W_ih2 h1[t] + W_hh2 h2[t-1] ======
        #pragma unroll
        for (int g = 0; g < 4; ++g) {
            u64 bz = pack2(sm[B2_O + g * 64 + hid], 0.f);
            #pragma unroll
            for (int b = 0; b < 8; ++b) acc[g][b] = bz;
        }
        #pragma unroll 4
        for (int kq = 0; kq < 16; ++kq) {
            ulonglong2 ha[8];
            #pragma unroll
            for (int b = 0; b < 8; ++b)
                ha[b] = *(const ulonglong2*)&h1b[b * 64 + 4 * kq];
            u64 w;
            w = *(const u64*)&w2p0[4 * kq];
            #pragma unroll
            for (int b = 0; b < 8; ++b) fma2(acc[0][b], w, ha[b].x);
            w = *(const u64*)&w2p1[4 * kq];
            #pragma unroll
            for (int b = 0; b < 8; ++b) fma2(acc[1][b], w, ha[b].x);
            w = *(const u64*)&w2p2[4 * kq];
            #pragma unroll
            for (int b = 0; b < 8; ++b) fma2(acc[2][b], w, ha[b].x);
            w = *(const u64*)&w2p3[4 * kq];
            #pragma unroll
            for (int b = 0; b < 8; ++b) fma2(acc[3][b], w, ha[b].x);
            w = *(const u64*)&w2p0[4 * kq + 2];
            #pragma unroll
            for (int b = 0; b < 8; ++b) fma2(acc[0][b], w, ha[b].y);
            w = *(const u64*)&w2p1[4 * kq + 2];
            #pragma unroll
            for (int b = 0; b < 8; ++b) fma2(acc[1][b], w, ha[b].y);
            w = *(const u64*)&w2p2[4 * kq + 2];
            #pragma unroll
            for (int b = 0; b < 8; ++b) fma2(acc[2][b], w, ha[b].y);
            w = *(const u64*)&w2p3[4 * kq + 2];
            #pragma unroll
            for (int b = 0; b < 8; ++b) fma2(acc[3][b], w, ha[b].y);
        }
        #pragma unroll 4
        for (int kq = 0; kq < 16; ++kq) {
            ulonglong2 ha[8];
            #pragma unroll
            for (int b = 0; b < 8; ++b)
                ha[b] = *(const ulonglong2*)&h2r[b * 64 + 4 * kq];
            u64 w;
            w = *(const u64*)&w2p0[64 + 4 * kq];
            #pragma unroll
            for (int b = 0; b < 8; ++b) fma2(acc[0][b], w, ha[b].x);
            w = *(const u64*)&w2p1[64 + 4 * kq];
            #pragma unroll
            for (int b = 0; b < 8; ++b) fma2(acc[1][b], w, ha[b].x);
            w = *(const u64*)&w2p2[64 + 4 * kq];
            #pragma unroll
            for (int b = 0; b < 8; ++b) fma2(acc[2][b], w, ha[b].x);
            w = *(const u64*)&w2p3[64 + 4 * kq];
            #pragma unroll
            for (int b = 0; b < 8; ++b) fma2(acc[3][b], w, ha[b].x);
            w = *(const u64*)&w2p0[64 + 4 * kq + 2];
            #pragma unroll
            for (int b = 0; b < 8; ++b) fma2(acc[0][b], w, ha[b].y);
            w = *(const u64*)&w2p1[64 + 4 * kq + 2];
            #pragma unroll
            for (int b = 0; b < 8; ++b) fma2(acc[1][b], w, ha[b].y);
            w = *(const u64*)&w2p2[64 + 4 * kq + 2];
            #pragma unroll
            for (int b = 0; b < 8; ++b) fma2(acc[2][b], w, ha[b].y);
            w = *(const u64*)&w2p3[64 + 4 * kq + 2];
            #pragma unroll
            for (int b = 0; b < 8; ++b) fma2(acc[3][b], w, ha[b].y);
        }

        // ---- PW2: h2[t] -> ping-pong write buffer ----
        #pragma unroll
        for (int b = 0; b < 8; ++b) {
            float zi = lo32(acc[0][b]) + hi32(acc[0][b]);
            float zf = lo32(acc[1][b]) + hi32(acc[1][b]);
            float zg = lo32(acc[2][b]) + hi32(acc[2][b]);
            float zo = lo32(acc[3][b]) + hi32(acc[3][b]);
            float cc = sigf(zf) * c2[b] + sigf(zi) * tanhf_(zg);
            c2[b] = cc;
            h2w[b * 64 + hstore] = sigf(zo) * tanhf_(cc);
        }

        // ============ GEMM1(t+1): z1 = b1 + x[t+1] w_ih1 + W_hh1 h1[t] =====
        if (t + 1 < SEQ) {
            const int tt = (t + 1) & 15;
            float4 xa = *(const float4*)&sm[XT_O + tt * 36 + bg * 8];
            float4 xb = *(const float4*)&sm[XT_O + tt * 36 + bg * 8 + 4];
            float xv[8] = { xa.x, xa.y, xa.z, xa.w, xb.x, xb.y, xb.z, xb.w };
            #pragma unroll
            for (int g = 0; g < 4; ++g) {
                float wg = sm[WI1_O + g * 64 + hid], bb = sm[B1_O + g * 64 + hid];
                #pragma unroll
                for (int b = 0; b < 8; ++b)
                    acc[g][b] = pack2(fmaf(xv[b], wg, bb), 0.f);
            }
            #pragma unroll 4
            for (int kq = 0; kq < 16; ++kq) {
                ulonglong2 ha[8];
                #pragma unroll
                for (int b = 0; b < 8; ++b)
                    ha[b] = *(const ulonglong2*)&h1b[b * 64 + 4 * kq];
                u64 w;
                w = *(const u64*)&w1p0[4 * kq];
                #pragma unroll
                for (int b = 0; b < 8; ++b) fma2(acc[0][b], w, ha[b].x);
                w = *(const u64*)&w1p1[4 * kq];
                #pragma unroll
                for (int b = 0; b < 8; ++b) fma2(acc[1][b], w, ha[b].x);
                w = *(const u64*)&w1p2[4 * kq];
                #pragma unroll
                for (int b = 0; b < 8; ++b) fma2(acc[2][b], w, ha[b].x);
                w = *(const u64*)&w1p3[4 * kq];
                #pragma unroll
                for (int b = 0; b < 8; ++b) fma2(acc[3][b], w, ha[b].x);
                w = *(const u64*)&w1p0[4 * kq + 2];
                #pragma unroll
                for (int b = 0; b < 8; ++b) fma2(acc[0][b], w, ha[b].y);
                w = *(const u64*)&w1p1[4 * kq + 2];
                #pragma unroll
                for (int b = 0; b < 8; ++b) fma2(acc[1][b], w, ha[b].y);
                w = *(const u64*)&w1p2[4 * kq + 2];
                #pragma unroll
                for (int b = 0; b < 8; ++b) fma2(acc[2][b], w, ha[b].y);
                w = *(const u64*)&w1p3[4 * kq + 2];
                #pragma unroll
                for (int b = 0; b < 8; ++b) fma2(acc[3][b], w, ha[b].y);
            }
        }
        __syncthreads();   // all reads of h1[t] complete

        if (t + 1 < SEQ) {
            #pragma unroll
            for (int b = 0; b < 8; ++b) {
                float zi = lo32(acc[0][b]) + hi32(acc[0][b]);
                float zf = lo32(acc[1][b]) + hi32(acc[1][b]);
                float zg = lo32(acc[2][b]) + hi32(acc[2][b]);
                float zo = lo32(acc[3][b]) + hi32(acc[3][b]);
                float cc = sigf(zf) * c1[b] + sigf(zi) * tanhf_(zg);
                c1[b] = cc;
                h1b[b * 64 + hstore] = sigf(zo) * tanhf_(cc);
            }
        }
        __syncthreads();   // h1[t+1], h2[t] published
    }

    // ---- dense head on h2[511] (in H2A: t=511 odd -> wrote A) ----
    for (int i = tid; i < 2048; i += NT) sm[W1_O + i] = W_d1[i];
    for (int i = tid; i < 768;  i += NT) sm[W1_O + 2048 + i] = W_d2[i];
    if (tid < 32) sm[W1_O + 2816 + tid] = b_d1[tid];
    if (tid < 24) sm[W1_O + 2848 + tid] = b_d2[tid];
    __syncthreads();

    for (int idx = tid; idx < 1024; idx += NT) {        // relu(h2 @ W_d1^T + b)
        int b = idx >> 5, j = idx & 31;
        float a = sm[W1_O + 2816 + j];
        #pragma unroll 8
        for (int k = 0; k < 64; ++k)
            a += sm[H2A_O + b * 64 + k] * sm[W1_O + j * 64 + k];
        sm[H1_O + b * 32 + j] = fmaxf(a, 0.f);
    }
    __syncthreads();
    for (int idx = tid; idx < 768; idx += NT) {         // y1 @ W_d2^T + b
        int b = idx / 24, o = idx - b * 24;
        float a = sm[W1_O + 2848 + o];
        #pragma unroll 8
        for (int j = 0; j < 32; ++j)
            a += sm[H1_O + b * 32 + j] * sm[W1_O + 2048 + o * 32 + j];
        out[(size_t)(b0 + b) * 24 + o] = a;
    }
}

extern "C" void kernel_launch(void* const* d_in, const int* in_sizes, int n_in,
                              void* d_out, int out_size)
{
    const float* x     = (const float*)d_in[0];
    const float* W_ih1 = (const float*)d_in[1];
    const float* W_hh1 = (const float*)d_in[2];
    const float* b_ih1 = (const float*)d_in[3];
    const float* b_hh1 = (const float*)d_in[4];
    const float* W_ih2 = (const float*)d_in[5];
    const float* W_hh2 = (const float*)d_in[6];
    const float* b_ih2 = (const float*)d_in[7];
    const float* b_hh2 = (const float*)d_in[8];
    const float* W_d1  = (const float*)d_in[9];
    const float* b_d1  = (const float*)d_in[10];
    const float* W_d2  = (const float*)d_in[11];
    const float* b_d2  = (const float*)d_in[12];
    float* out = (float*)d_out;

    cudaFuncSetAttribute(lstm_fused_kernel,
                         cudaFuncAttributeMaxDynamicSharedMemorySize, SM_BYTES);
    lstm_fused_kernel<<<NBLK, NT, SM_BYTES>>>(
        x, W_ih1, W_hh1, b_ih1, b_hh1, W_ih2, W_hh2, b_ih2, b_hh2,
        W_d1, b_d1, W_d2, b_d2, out);
}